// round 15
// baseline (speedup 1.0000x reference)
#include <cuda_runtime.h>
#include <cuda_fp16.h>
#include <math.h>

#define VOL (128*128*128)          // 2^21
#define NB 8                        // batch*channels
#define NU1 2048                    // pass-1 units (8 vols * 128 z * 2 ytiles)
#define NUNITS (NB * 65)            // 520 pass-2 units

// Packed spectra FFT(o + i*t): [vol][p][z][y] where plane p holds true kx=rev7(p)
__device__ __half2 g_ft[(size_t)NB * VOL];
// Accumulators: c3*520 + shell*8 + bc
__device__ float g_acc[3 * 65 * NB];
__device__ unsigned g_done;
__device__ unsigned g_u1;            // pass-1 work counter
__device__ unsigned g_u2;            // pass-2 work counter
__device__ unsigned g_vol_done[NB];  // pass-1 completion per volume (256 each)

__device__ __forceinline__ int rev5(int i) { return (int)(__brev((unsigned)i) >> 27); }
__device__ __forceinline__ int rev7(int i) { return (int)(__brev((unsigned)i) >> 25); }

// ===========================================================================
// fp16 twiddle tables. Twiddle stored as pair (wr,wr),(-wi,wi).
// The 1/sqrt(128) ortho scale is folded into the m=2 stage table (twS[3]).
struct __align__(8) h2pair { __half2 rr, ii; };
#define TABS_H (64 + 32 + 128)

__device__ __forceinline__ void init_tabs_h(h2pair* twA, h2pair* twB, h2pair* twS, int tid) {
    const float K = -0.04908738521234052f;   // -2*pi/128
    const float SC = 0.08838834764831845f;   // 1/sqrt(128)
    if (tid < 64) {
        float sv, cv; sincosf(K * (float)tid, &sv, &cv);
        twA[tid].rr = __floats2half2_rn(cv, cv);
        twA[tid].ii = __floats2half2_rn(-sv, sv);
    }
    if (tid < 32) {
        float sv, cv; sincosf(K * (float)(2 * tid), &sv, &cv);
        twB[tid].rr = __floats2half2_rn(cv, cv);
        twB[tid].ii = __floats2half2_rn(-sv, sv);
#pragma unroll
        for (int j = 0; j < 4; j++) {
            int m = 16 >> j;
            float c2 = 1.0f, s2 = 0.0f;
            if (tid & m) {
                int idx = (tid & (m - 1)) * (64 / m);
                sincosf(K * (float)idx, &s2, &c2);
            }
            float g = (j == 3) ? SC : 1.0f;    // fold ortho scale into m=2 stage
            twS[j * 32 + tid].rr = __floats2half2_rn(c2 * g, c2 * g);
            twS[j * 32 + tid].ii = __floats2half2_rn(-s2 * g, s2 * g);
        }
    }
}

__device__ __forceinline__ __half2 cmul_h(h2pair w, __half2 v) {
    return __hfma2(w.ii, __lowhigh2highlow(v), __hmul2(w.rr, v));
}
__device__ __forceinline__ __half2 shflx_h2(__half2 v, int m) {
    unsigned u = *reinterpret_cast<unsigned*>(&v);
    u = __shfl_xor_sync(0xffffffffu, u, m);
    return *reinterpret_cast<__half2*>(&u);
}
__device__ __forceinline__ __half2 sgn_h2(int hi) {
    unsigned u = hi ? 0xBC00BC00u : 0x3C003C00u;   // (-1,-1) : (1,1)
    return *reinterpret_cast<__half2*>(&u);
}
__device__ __forceinline__ __half2 conj_h2(__half2 v) {
    unsigned c = 0xBC003C00u;                      // (1, -1)
    return __hmul2(v, *reinterpret_cast<__half2*>(&c));
}

// TWO interleaved 128-pt DIF FFTs in fp16x2 (shared twiddles, 2x ILP).
// Slot (lane,r) holds x[lane+32r] in, sc*X[rev7(lane+32r)] out.
__device__ __forceinline__ void dif_fft128_h2(__half2 v[4], __half2 u[4], int lane,
        const h2pair* twA, const h2pair* twB, const h2pair* twS) {
    __half2 a, b;
    {
        h2pair w0 = twA[lane], w1 = twA[lane + 32];
        a = v[0]; b = v[2]; v[0] = __hadd2(a, b); v[2] = cmul_h(w0, __hsub2(a, b));
        a = u[0]; b = u[2]; u[0] = __hadd2(a, b); u[2] = cmul_h(w0, __hsub2(a, b));
        a = v[1]; b = v[3]; v[1] = __hadd2(a, b); v[3] = cmul_h(w1, __hsub2(a, b));
        a = u[1]; b = u[3]; u[1] = __hadd2(a, b); u[3] = cmul_h(w1, __hsub2(a, b));
    }
    {
        h2pair w0 = twB[lane];
        a = v[0]; b = v[1]; v[0] = __hadd2(a, b); v[1] = cmul_h(w0, __hsub2(a, b));
        a = v[2]; b = v[3]; v[2] = __hadd2(a, b); v[3] = cmul_h(w0, __hsub2(a, b));
        a = u[0]; b = u[1]; u[0] = __hadd2(a, b); u[1] = cmul_h(w0, __hsub2(a, b));
        a = u[2]; b = u[3]; u[2] = __hadd2(a, b); u[3] = cmul_h(w0, __hsub2(a, b));
    }
#pragma unroll
    for (int j = 0; j < 4; j++) {
        int m = 16 >> j;
        __half2 sg = sgn_h2(lane & m);
        h2pair wj = twS[j * 32 + lane];
#pragma unroll
        for (int r = 0; r < 4; r++) {
            __half2 o1 = shflx_h2(v[r], m);
            __half2 o2 = shflx_h2(u[r], m);
            v[r] = cmul_h(wj, __hfma2(sg, v[r], o1));
            u[r] = cmul_h(wj, __hfma2(sg, u[r], o2));
        }
    }
    {
        __half2 sg = sgn_h2(lane & 1);
#pragma unroll
        for (int r = 0; r < 4; r++) {
            __half2 o1 = shflx_h2(v[r], 1);
            __half2 o2 = shflx_h2(u[r], 1);
            v[r] = __hfma2(sg, v[r], o1);
            u[r] = __hfma2(sg, u[r], o2);
        }
    }
}

// ---------------------------------------------------------------------------
// Fused persistent kernel: phase 1 (x-FFT, transposed store) then phase 2
// (y-FFT + z-FFT + shell reduce), with per-volume readiness gating.
#define SMEM2 (TABS_H * 8 + 2 * 128 * 129 * 4 + 32 * 196 * 4)

__global__ void __launch_bounds__(1024, 1) k_fsc_all(const float* __restrict__ a_in,
                                                     const float* __restrict__ b_in,
                                                     float* __restrict__ out) {
    extern __shared__ unsigned char smem_raw[];
    h2pair*  tabs = (h2pair*)smem_raw;
    h2pair*  twA = tabs; h2pair* twB = tabs + 64; h2pair* twS = tabs + 96;
    __half2* pA   = (__half2*)(tabs + TABS_H);            // [z][y] pitch 129
    __half2* pBs  = pA + 128 * 129;
    float*   bins = (float*)(pBs + 128 * 129);            // [warp][196]
    __shared__ unsigned s_unit;
    __shared__ bool s_last;
    __shared__ float red[NB];

    int tid = threadIdx.x, lane = tid & 31, w = tid >> 5;
    init_tabs_h(twA, twB, twS, tid);

    // ======================= PHASE 1: x-FFT ===============================
    // tile[64][129] reuses the pA region (33 KB < 66 KB)
    __half2* tile = pA;
    for (;;) {
        if (tid == 0) s_unit = atomicAdd(&g_u1, 1u);
        __syncthreads();                       // also covers tabs on first iter
        unsigned b = s_unit;
        if (b >= NU1) break;

        unsigned ytile = b & 1u;
        unsigned z     = (b >> 1) & 127u;
        unsigned vol   = b >> 8;               // vol-major claim order

        size_t off = (size_t)vol * VOL + (size_t)z * 16384
                   + (size_t)(ytile * 64 + w) * 128;
        const float* so = a_in + off;
        const float* st = b_in + off;

        __half2 v[4], u[4];
#pragma unroll
        for (int r = 0; r < 4; r++) {
            v[r] = __floats2half2_rn(so[lane + 32 * r],        st[lane + 32 * r]);
            u[r] = __floats2half2_rn(so[lane + 32 * r + 4096], st[lane + 32 * r + 4096]);
        }
        dif_fft128_h2(v, u, lane, twA, twB, twS);

#pragma unroll
        for (int r = 0; r < 4; r++) {
            tile[w * 129 + lane + 32 * r]        = v[r];
            tile[(w + 32) * 129 + lane + 32 * r] = u[r];
        }
        __syncthreads();

        size_t base = (size_t)vol * VOL + (size_t)z * 128 + ytile * 64 + lane;
#pragma unroll
        for (int xi = 0; xi < 4; xi++) {
            int p = w * 4 + xi;               // bit-reversed kx label
            g_ft[base + (size_t)p * 16384]      = tile[lane * 129 + p];
            g_ft[base + (size_t)p * 16384 + 32] = tile[(lane + 32) * 129 + p];
        }

        // publish: all threads' stores fenced, then one release increment
        __threadfence();
        __syncthreads();
        if (tid == 0) atomicAdd(&g_vol_done[vol], 1u);
    }

    // ======================= PHASE 2: y+z FFT + reduce ====================
    int qz = rev5(lane);
    int fzv[4];
    {
        int kzv[4] = { 4 * qz, 4 * qz + 2, 4 * qz + 1, 4 * qz + 3 };
#pragma unroll
        for (int r = 0; r < 4; r++) fzv[r] = (kzv[r] >= 64) ? kzv[r] - 128 : kzv[r];
    }
    float* mybins = bins + w * 196;

    for (;;) {
        // fetch next unit (tid 0 also waits for its volume to be ready)
        if (tid == 0) {
            unsigned uu = atomicAdd(&g_u2, 1u);
            s_unit = uu;
            if (uu < NUNITS) {
                unsigned bcw = uu / 65;
                while (atomicAdd(&g_vol_done[bcw], 0u) < 256u) __nanosleep(64);
                __threadfence();               // acquire: g_ft of vol bcw visible
            }
        }
        for (int i = tid; i < 32 * 196; i += 1024) bins[i] = 0.0f;
        __syncthreads();
        unsigned unit = s_unit;
        if (unit >= NUNITS) break;

        unsigned bc  = unit / 65;
        unsigned kx1 = unit % 65;                       // true kx 0..64
        unsigned kx2 = (128u - kx1) & 127u;
        bool dual = (kx2 != kx1);
        int p1 = rev7((int)kx1), p2 = rev7((int)kx2);
        __half2* pB = dual ? pBs : pA;

        const __half2* gA = g_ft + ((size_t)bc * 128 + p1) * 16384;
        const __half2* gB = g_ft + ((size_t)bc * 128 + p2) * 16384;

        // y-FFT: rows read straight from global, results to smem.
        if (dual) {
#pragma unroll
            for (int i = 0; i < 4; i++) {
                int z = w + 32 * i;
                __half2 v[4], u[4];
#pragma unroll
                for (int r = 0; r < 4; r++) {
                    v[r] = gA[z * 128 + lane + 32 * r];
                    u[r] = gB[z * 128 + lane + 32 * r];
                }
                dif_fft128_h2(v, u, lane, twA, twB, twS);
#pragma unroll
                for (int r = 0; r < 4; r++) {
                    pA [z * 129 + lane + 32 * r] = v[r];
                    pBs[z * 129 + lane + 32 * r] = u[r];
                }
            }
        } else {
#pragma unroll
            for (int i = 0; i < 2; i++) {
                int z0 = w + 64 * i, z1 = z0 + 32;
                __half2 v[4], u[4];
#pragma unroll
                for (int r = 0; r < 4; r++) {
                    v[r] = gA[z0 * 128 + lane + 32 * r];
                    u[r] = gA[z1 * 128 + lane + 32 * r];
                }
                dif_fft128_h2(v, u, lane, twA, twB, twS);
#pragma unroll
                for (int r = 0; r < 4; r++) {
                    pA[z0 * 129 + lane + 32 * r] = v[r];
                    pA[z1 * 129 + lane + 32 * r] = u[r];
                }
            }
        }
        __syncthreads();

        // z-FFT (fp16, registers). Mirror value F(-k) via FFT of the
        // CONJUGATED mirror column; conj folds into O/T sign flips.
        // slot (lane,r) holds kz = 4*rev5(lane) + {0,2,1,3}[r]
        int fx = (int)kx1; if (fx >= 64) fx -= 128;
        float cfac = dual ? 0.5f : 0.25f;     // z-norm inside the FFT scale

#pragma unroll
        for (int i = 0; i < 4; i++) {
            int pyA = w + 32 * i;                 // column position (bit-reversed ky)
            int kyA = rev7(pyA);
            int fy = (kyA >= 64) ? kyA - 128 : kyA;
            int fxy2 = fx * fx + fy * fy;
            if (fxy2 > 4224) continue;            // no shell <= 64 (warp-uniform)
            int pyB = rev7((128 - kyA) & 127);

            __half2 va[4], vh[4];
#pragma unroll
            for (int r = 0; r < 4; r++) {
                va[r] = pA[(lane + 32 * r) * 129 + pyA];
                vh[r] = conj_h2(pB[(lane + 32 * r) * 129 + pyB]);
            }
            dif_fft128_h2(va, vh, lane, twA, twB, twS);

#pragma unroll
            for (int r = 0; r < 4; r++) {
                int r2 = fzv[r] * fzv[r] + fxy2;
                int sh = (int)sqrtf((float)r2);    // exact truncation
                if (sh <= 64) {
                    float2 F = __half22float2(va[r]);
                    float2 H = __half22float2(vh[r]);   // H = conj(F(-k))
                    float Ox = F.x + H.x, Oy = F.y + H.y;   // 2*O
                    float Tx = F.y - H.y, Ty = H.x - F.x;   // 2*T
                    atomicAdd(&mybins[sh * 3 + 0], Ox * Tx + Oy * Ty);
                    atomicAdd(&mybins[sh * 3 + 1], Ox * Ox + Oy * Oy);
                    atomicAdd(&mybins[sh * 3 + 2], Tx * Tx + Ty * Ty);
                }
            }
        }
        __syncthreads();

        // fold per-warp bins -> global accumulators (cfac applied once here)
        if (tid < 195) {
            float s = 0.0f;
#pragma unroll
            for (int ww = 0; ww < 32; ww++) s += bins[ww * 196 + tid];
            int sh = tid / 3, c3 = tid % 3;
            atomicAdd(&g_acc[c3 * 520 + sh * 8 + bc], s * cfac);
        }
        __syncthreads();    // fold reads complete before next unit's zeroing
    }

    // ================= FINALIZE (last block) + state reset ================
    if (tid == 0) {
        __threadfence();
        unsigned old = atomicAdd(&g_done, 1u);
        s_last = (old == gridDim.x - 1);
    }
    __syncthreads();
    if (!s_last) return;

    float* sacc = bins;
    for (int i = tid; i < 3 * 65 * NB; i += 1024)
        sacc[i] = atomicExch(&g_acc[i], 0.0f);
    __syncthreads();

    if (tid < NB) {
        float acc = 0.0f;
        for (int s = 1; s <= 64; s++) {
            float n  = sacc[0 * 520 + s * 8 + tid];
            float po = sacc[1 * 520 + s * 8 + tid];
            float pt = sacc[2 * 520 + s * 8 + tid];
            float f = n / sqrtf(po * pt + 1e-6f);
            acc += fminf(1.0f, fmaxf(-1.0f, f));
        }
        red[tid] = 1.0f - acc * (1.0f / 64.0f);
        atomicExch(&g_vol_done[tid], 0u);      // reset for next graph replay
    }
    __syncthreads();
    if (tid == 0) {
        float m = 0.0f;
#pragma unroll
        for (int i = 0; i < NB; i++) m += red[i];
        out[0] = m * (1.0f / (float)NB);
        atomicExch(&g_u1, 0u);
        atomicExch(&g_u2, 0u);
        atomicExch(&g_done, 0u);
    }
}

// ---------------------------------------------------------------------------
extern "C" void kernel_launch(void* const* d_in, const int* in_sizes, int n_in,
                              void* d_out, int out_size) {
    const float* model_output = (const float*)d_in[0];
    const float* target       = (const float*)d_in[1];

    static int nsm = 0;
    if (nsm == 0) {
        int dev = 0;
        cudaGetDevice(&dev);
        if (cudaDeviceGetAttribute(&nsm, cudaDevAttrMultiProcessorCount, dev)
                != cudaSuccess || nsm <= 0)
            nsm = 148;
    }

    cudaFuncSetAttribute(k_fsc_all,
                         cudaFuncAttributeMaxDynamicSharedMemorySize, SMEM2);

    k_fsc_all<<<nsm, 1024, SMEM2>>>(model_output, target, (float*)d_out);
}

// round 16
// speedup vs baseline: 1.0434x; 1.0434x over previous
#include <cuda_runtime.h>
#include <cuda_fp16.h>
#include <math.h>

#define VOL (128*128*128)          // 2^21
#define NB 8                        // batch*channels
#define NUNITS (NB * 65)            // 520 pass-2 units

// Packed spectra FFT(o + i*t): [vol][p][z][y] where plane p holds true kx=rev7(p)
__device__ __half2 g_ft[(size_t)NB * VOL];
// Accumulators: c3*520 + shell*8 + bc
__device__ float g_acc[3 * 65 * NB];
__device__ unsigned g_done;
__device__ unsigned g_u2;            // pass-2 work counter (reset by finalizer)

__device__ __forceinline__ int rev5(int i) { return (int)(__brev((unsigned)i) >> 27); }
__device__ __forceinline__ int rev7(int i) { return (int)(__brev((unsigned)i) >> 25); }

// cluster helpers
__device__ __forceinline__ unsigned ctarank() {
    unsigned r; asm("mov.u32 %0, %%cluster_ctarank;" : "=r"(r)); return r;
}
__device__ __forceinline__ unsigned smem_a32(const void* p) {
    return (unsigned)__cvta_generic_to_shared(p);
}
__device__ __forceinline__ unsigned mapa_u32(unsigned addr, unsigned rank) {
    unsigned r; asm("mapa.shared::cluster.u32 %0, %1, %2;" : "=r"(r) : "r"(addr), "r"(rank));
    return r;
}
__device__ __forceinline__ void sts_cluster(unsigned addr, unsigned val) {
    asm volatile("st.shared::cluster.u32 [%0], %1;" :: "r"(addr), "r"(val) : "memory");
}
#define CLUSTER_SYNC() do { \
    asm volatile("barrier.cluster.arrive.aligned;" ::: "memory"); \
    asm volatile("barrier.cluster.wait.aligned;" ::: "memory"); } while (0)

// ===========================================================================
// fp16 twiddle tables. Twiddle stored as pair (wr,wr),(-wi,wi).
// The 1/sqrt(128) ortho scale is folded into the m=2 stage table (twS[3]).
struct __align__(8) h2pair { __half2 rr, ii; };
#define TABS_H (64 + 32 + 128)

__device__ __forceinline__ void init_tabs_h(h2pair* twA, h2pair* twB, h2pair* twS, int tid) {
    const float K = -0.04908738521234052f;   // -2*pi/128
    const float SC = 0.08838834764831845f;   // 1/sqrt(128)
    if (tid < 64) {
        float sv, cv; sincosf(K * (float)tid, &sv, &cv);
        twA[tid].rr = __floats2half2_rn(cv, cv);
        twA[tid].ii = __floats2half2_rn(-sv, sv);
    }
    if (tid < 32) {
        float sv, cv; sincosf(K * (float)(2 * tid), &sv, &cv);
        twB[tid].rr = __floats2half2_rn(cv, cv);
        twB[tid].ii = __floats2half2_rn(-sv, sv);
#pragma unroll
        for (int j = 0; j < 4; j++) {
            int m = 16 >> j;
            float c2 = 1.0f, s2 = 0.0f;
            if (tid & m) {
                int idx = (tid & (m - 1)) * (64 / m);
                sincosf(K * (float)idx, &s2, &c2);
            }
            float g = (j == 3) ? SC : 1.0f;    // fold ortho scale into m=2 stage
            twS[j * 32 + tid].rr = __floats2half2_rn(c2 * g, c2 * g);
            twS[j * 32 + tid].ii = __floats2half2_rn(-s2 * g, s2 * g);
        }
    }
}

__device__ __forceinline__ __half2 cmul_h(h2pair w, __half2 v) {
    return __hfma2(w.ii, __lowhigh2highlow(v), __hmul2(w.rr, v));
}
__device__ __forceinline__ __half2 shflx_h2(__half2 v, int m) {
    unsigned u = *reinterpret_cast<unsigned*>(&v);
    u = __shfl_xor_sync(0xffffffffu, u, m);
    return *reinterpret_cast<__half2*>(&u);
}
__device__ __forceinline__ __half2 sgn_h2(int hi) {
    unsigned u = hi ? 0xBC00BC00u : 0x3C003C00u;   // (-1,-1) : (1,1)
    return *reinterpret_cast<__half2*>(&u);
}
__device__ __forceinline__ __half2 conj_h2(__half2 v) {
    unsigned c = 0xBC003C00u;                      // (1, -1)
    return __hmul2(v, *reinterpret_cast<__half2*>(&c));
}
__device__ __forceinline__ unsigned h2u(__half2 v) { return *reinterpret_cast<unsigned*>(&v); }

// TWO interleaved 128-pt DIF FFTs in fp16x2 (shared twiddles, 2x ILP).
// Slot (lane,r) holds x[lane+32r] in, sc*X[rev7(lane+32r)] out.
__device__ __forceinline__ void dif_fft128_h2(__half2 v[4], __half2 u[4], int lane,
        const h2pair* twA, const h2pair* twB, const h2pair* twS) {
    __half2 a, b;
    {
        h2pair w0 = twA[lane], w1 = twA[lane + 32];
        a = v[0]; b = v[2]; v[0] = __hadd2(a, b); v[2] = cmul_h(w0, __hsub2(a, b));
        a = u[0]; b = u[2]; u[0] = __hadd2(a, b); u[2] = cmul_h(w0, __hsub2(a, b));
        a = v[1]; b = v[3]; v[1] = __hadd2(a, b); v[3] = cmul_h(w1, __hsub2(a, b));
        a = u[1]; b = u[3]; u[1] = __hadd2(a, b); u[3] = cmul_h(w1, __hsub2(a, b));
    }
    {
        h2pair w0 = twB[lane];
        a = v[0]; b = v[1]; v[0] = __hadd2(a, b); v[1] = cmul_h(w0, __hsub2(a, b));
        a = v[2]; b = v[3]; v[2] = __hadd2(a, b); v[3] = cmul_h(w0, __hsub2(a, b));
        a = u[0]; b = u[1]; u[0] = __hadd2(a, b); u[1] = cmul_h(w0, __hsub2(a, b));
        a = u[2]; b = u[3]; u[2] = __hadd2(a, b); u[3] = cmul_h(w0, __hsub2(a, b));
    }
#pragma unroll
    for (int j = 0; j < 4; j++) {
        int m = 16 >> j;
        __half2 sg = sgn_h2(lane & m);
        h2pair wj = twS[j * 32 + lane];
#pragma unroll
        for (int r = 0; r < 4; r++) {
            __half2 o1 = shflx_h2(v[r], m);
            __half2 o2 = shflx_h2(u[r], m);
            v[r] = cmul_h(wj, __hfma2(sg, v[r], o1));
            u[r] = cmul_h(wj, __hfma2(sg, u[r], o2));
        }
    }
    {
        __half2 sg = sgn_h2(lane & 1);
#pragma unroll
        for (int r = 0; r < 4; r++) {
            __half2 o1 = shflx_h2(v[r], 1);
            __half2 o2 = shflx_h2(u[r], 1);
            v[r] = __hfma2(sg, v[r], o1);
            u[r] = __hfma2(sg, u[r], o2);
        }
    }
}

// ---------------------------------------------------------------------------
// Pass 1: pack P = o + i*t (fp16), x-FFT fp16 (2 rows per warp, interleaved),
// transposed to [vol][p][z][y].  (unchanged from best kernel)
__global__ void __launch_bounds__(1024) k_fft_x(const float* __restrict__ a_in,
                                                const float* __restrict__ b_in) {
    __shared__ h2pair tabs[TABS_H];
    __shared__ __half2 tile[64][129];
    h2pair* twA = tabs; h2pair* twB = tabs + 64; h2pair* twS = tabs + 96;
    int tid = threadIdx.x, lane = tid & 31, w = tid >> 5;
    init_tabs_h(twA, twB, twS, tid);

    unsigned b = blockIdx.x;              // 8 vols * 128 z * 2 ytiles = 2048
    unsigned ytile = b & 1u;
    unsigned z     = (b >> 1) & 127u;
    unsigned vol   = b >> 8;

    size_t off = (size_t)vol * VOL + (size_t)z * 16384 + (size_t)(ytile * 64 + w) * 128;
    const float* so = a_in + off;
    const float* st = b_in + off;
    __syncthreads();

    __half2 v[4], u[4];
#pragma unroll
    for (int r = 0; r < 4; r++) {
        v[r] = __floats2half2_rn(so[lane + 32 * r],        st[lane + 32 * r]);
        u[r] = __floats2half2_rn(so[lane + 32 * r + 4096], st[lane + 32 * r + 4096]);
    }
    dif_fft128_h2(v, u, lane, twA, twB, twS);

#pragma unroll
    for (int r = 0; r < 4; r++) {
        tile[w][lane + 32 * r]      = v[r];
        tile[w + 32][lane + 32 * r] = u[r];
    }
    __syncthreads();

    size_t base = (size_t)vol * VOL + (size_t)z * 128 + ytile * 64 + lane;
#pragma unroll
    for (int xi = 0; xi < 4; xi++) {
        int p = w * 4 + xi;               // bit-reversed kx label
        g_ft[base + (size_t)p * 16384]      = tile[lane][p];
        g_ft[base + (size_t)p * 16384 + 32] = tile[lane + 32][p];
    }
}

// ---------------------------------------------------------------------------
// Pass 2 (CLUSTERED, persistent): each 2-CTA cluster processes one (bc,kx-pair)
// unit. CTA rank r owns column-half [64r, 64r+64) of BOTH planes (the halves
// are closed under Hermitian mirror pairing: pyA<64 <=> pyB<64). Each CTA
// y-FFTs one plane, scattering output halves locally / to the peer via DSMEM
// stores; z-FFT + shell reduce then run on purely local data.
// Dynamic smem: tabs 1792 + Ahalf 33280 + Bhalf 33280 + bins 25088 = 93440
#define HPITCH 65
#define SMEM2C (TABS_H * 8 + 2 * 128 * HPITCH * 4 + 32 * 196 * 4)

__global__ void __launch_bounds__(1024, 1) __cluster_dims__(2, 1, 1)
k_fft_yz_reduce(float* __restrict__ out) {
    extern __shared__ unsigned char smem_raw[];
    h2pair*  tabs  = (h2pair*)smem_raw;
    h2pair*  twA = tabs; h2pair* twB = tabs + 64; h2pair* twS = tabs + 96;
    __half2* Ahalf = (__half2*)(tabs + TABS_H);           // [z][y_local] pitch 65
    __half2* Bhalf = Ahalf + 128 * HPITCH;
    float*   bins  = (float*)(Bhalf + 128 * HPITCH);      // [warp][196]
    __shared__ unsigned s_unit;
    __shared__ bool s_last;
    __shared__ float red[NB];

    int tid = threadIdx.x, lane = tid & 31, w = tid >> 5;
    unsigned rank = ctarank(), peer = rank ^ 1u;
    init_tabs_h(twA, twB, twS, tid);

    // peer-base addresses (byte) of the half arrays and s_unit
    unsigned remA = mapa_u32(smem_a32(Ahalf), peer);
    unsigned remB = mapa_u32(smem_a32(Bhalf), peer);
    unsigned remU = mapa_u32(smem_a32(&s_unit), peer);
    unsigned locA = smem_a32(Ahalf), locB = smem_a32(Bhalf);

    int qz = rev5(lane);
    int fzv[4];
    {
        int kzv[4] = { 4 * qz, 4 * qz + 2, 4 * qz + 1, 4 * qz + 3 };
#pragma unroll
        for (int r = 0; r < 4; r++) fzv[r] = (kzv[r] >= 64) ? kzv[r] - 128 : kzv[r];
    }
    float* mybins = bins + w * 196;

    for (;;) {
        if (rank == 0 && tid == 0) {
            unsigned uu = atomicAdd(&g_u2, 1u);
            s_unit = uu;
            sts_cluster(remU, uu);
        }
        CLUSTER_SYNC();                     // claim visible; prev unit's smem reads done
        unsigned unit = s_unit;
        if (unit >= NUNITS) break;

        for (int i = tid; i < 32 * 196; i += 1024) bins[i] = 0.0f;

        unsigned bc  = unit / 65;
        unsigned kx1 = unit % 65;                       // true kx 0..64
        unsigned kx2 = (128u - kx1) & 127u;
        bool dual = (kx2 != kx1);
        int p1 = rev7((int)kx1), p2 = rev7((int)kx2);

        // ---- y-FFT: this CTA's plane (rank0: A, rank1: B); scatter halves ----
        {
            int myp = dual ? (rank ? p2 : p1) : p1;
            const __half2* gP = g_ft + ((size_t)bc * 128 + myp) * 16384;
#pragma unroll
            for (int i = 0; i < 2; i++) {
                int z0 = w + 64 * i, z1 = z0 + 32;
                __half2 v[4], u[4];
#pragma unroll
                for (int r = 0; r < 4; r++) {
                    v[r] = gP[z0 * 128 + lane + 32 * r];
                    u[r] = gP[z1 * 128 + lane + 32 * r];
                }
                dif_fft128_h2(v, u, lane, twA, twB, twS);

                if (dual) {
                    if (rank == 0) {      // plane A: lo half local, hi half remote
                        Ahalf[z0 * HPITCH + lane]      = v[0];
                        Ahalf[z0 * HPITCH + lane + 32] = v[1];
                        Ahalf[z1 * HPITCH + lane]      = u[0];
                        Ahalf[z1 * HPITCH + lane + 32] = u[1];
                        sts_cluster(remA + (z0 * HPITCH + lane) * 4,      h2u(v[2]));
                        sts_cluster(remA + (z0 * HPITCH + lane + 32) * 4, h2u(v[3]));
                        sts_cluster(remA + (z1 * HPITCH + lane) * 4,      h2u(u[2]));
                        sts_cluster(remA + (z1 * HPITCH + lane + 32) * 4, h2u(u[3]));
                    } else {              // plane B: lo half remote, hi half local
                        sts_cluster(remB + (z0 * HPITCH + lane) * 4,      h2u(v[0]));
                        sts_cluster(remB + (z0 * HPITCH + lane + 32) * 4, h2u(v[1]));
                        sts_cluster(remB + (z1 * HPITCH + lane) * 4,      h2u(u[0]));
                        sts_cluster(remB + (z1 * HPITCH + lane + 32) * 4, h2u(u[1]));
                        Bhalf[z0 * HPITCH + lane]      = v[2];
                        Bhalf[z0 * HPITCH + lane + 32] = v[3];
                        Bhalf[z1 * HPITCH + lane]      = u[2];
                        Bhalf[z1 * HPITCH + lane + 32] = u[3];
                    }
                } else {
                    // self-mirror plane: keep own half into BOTH local arrays
                    int rb = rank ? 2 : 0;
                    Ahalf[z0 * HPITCH + lane]      = v[rb];
                    Ahalf[z0 * HPITCH + lane + 32] = v[rb + 1];
                    Ahalf[z1 * HPITCH + lane]      = u[rb];
                    Ahalf[z1 * HPITCH + lane + 32] = u[rb + 1];
                    Bhalf[z0 * HPITCH + lane]      = v[rb];
                    Bhalf[z0 * HPITCH + lane + 32] = v[rb + 1];
                    Bhalf[z1 * HPITCH + lane]      = u[rb];
                    Bhalf[z1 * HPITCH + lane + 32] = u[rb + 1];
                }
            }
        }
        CLUSTER_SYNC();                   // halves complete (incl. peer's writes)

        // ---- z-FFT + Hermitian reduce on local halves (2 columns per warp) ----
        int fx = (int)kx1; if (fx >= 64) fx -= 128;
        float cfac = dual ? 0.5f : 0.25f;

#pragma unroll
        for (int i = 0; i < 2; i++) {
            int pyl = w + 32 * i;                 // local column 0..63
            int pyA = pyl + (int)(rank << 6);
            int kyA = rev7(pyA);
            int fy = (kyA >= 64) ? kyA - 128 : kyA;
            int fxy2 = fx * fx + fy * fy;
            if (fxy2 > 4224) continue;            // no shell <= 64 (warp-uniform)
            int pyBl = rev7((128 - kyA) & 127) - (int)(rank << 6);

            __half2 va[4], vh[4];
#pragma unroll
            for (int r = 0; r < 4; r++) {
                va[r] = Ahalf[(lane + 32 * r) * HPITCH + pyl];
                vh[r] = conj_h2(Bhalf[(lane + 32 * r) * HPITCH + pyBl]);
            }
            dif_fft128_h2(va, vh, lane, twA, twB, twS);

#pragma unroll
            for (int r = 0; r < 4; r++) {
                int r2 = fzv[r] * fzv[r] + fxy2;
                int sh = (int)sqrtf((float)r2);    // exact truncation
                if (sh <= 64) {
                    float2 F = __half22float2(va[r]);
                    float2 H = __half22float2(vh[r]);   // H = conj(F(-k))
                    float Ox = F.x + H.x, Oy = F.y + H.y;   // 2*O
                    float Tx = F.y - H.y, Ty = H.x - F.x;   // 2*T
                    atomicAdd(&mybins[sh * 3 + 0], Ox * Tx + Oy * Ty);
                    atomicAdd(&mybins[sh * 3 + 1], Ox * Ox + Oy * Oy);
                    atomicAdd(&mybins[sh * 3 + 2], Tx * Tx + Ty * Ty);
                }
            }
        }
        __syncthreads();

        // fold this CTA's bins -> global accumulators
        if (tid < 195) {
            float s = 0.0f;
#pragma unroll
            for (int ww = 0; ww < 32; ww++) s += bins[ww * 196 + tid];
            int sh = tid / 3, c3 = tid % 3;
            atomicAdd(&g_acc[c3 * 520 + sh * 8 + bc], s * cfac);
        }
        // loop-top CLUSTER_SYNC orders fold reads before next unit's zeroing
    }

    // ---- finalize (last CTA) + state reset (graph-replay safe) ----
    if (tid == 0) {
        __threadfence();
        unsigned old = atomicAdd(&g_done, 1u);
        s_last = (old == gridDim.x - 1);
    }
    __syncthreads();
    if (!s_last) return;

    float* sacc = bins;
    for (int i = tid; i < 3 * 65 * NB; i += 1024)
        sacc[i] = atomicExch(&g_acc[i], 0.0f);
    __syncthreads();

    if (tid < NB) {
        float acc = 0.0f;
        for (int s = 1; s <= 64; s++) {
            float n  = sacc[0 * 520 + s * 8 + tid];
            float po = sacc[1 * 520 + s * 8 + tid];
            float pt = sacc[2 * 520 + s * 8 + tid];
            float f = n / sqrtf(po * pt + 1e-6f);
            acc += fminf(1.0f, fmaxf(-1.0f, f));
        }
        red[tid] = 1.0f - acc * (1.0f / 64.0f);
    }
    __syncthreads();
    if (tid == 0) {
        float m = 0.0f;
#pragma unroll
        for (int i = 0; i < NB; i++) m += red[i];
        out[0] = m * (1.0f / (float)NB);
        atomicExch(&g_u2, 0u);
        atomicExch(&g_done, 0u);
    }
}

// ---------------------------------------------------------------------------
extern "C" void kernel_launch(void* const* d_in, const int* in_sizes, int n_in,
                              void* d_out, int out_size) {
    const float* model_output = (const float*)d_in[0];
    const float* target       = (const float*)d_in[1];

    static int nsm = 0;
    if (nsm == 0) {
        int dev = 0;
        cudaGetDevice(&dev);
        if (cudaDeviceGetAttribute(&nsm, cudaDevAttrMultiProcessorCount, dev)
                != cudaSuccess || nsm <= 0)
            nsm = 148;
        nsm &= ~1;                        // even grid for cluster size 2
    }

    cudaFuncSetAttribute(k_fft_yz_reduce,
                         cudaFuncAttributeMaxDynamicSharedMemorySize, SMEM2C);

    k_fft_x<<<8 * 128 * 2, 1024>>>(model_output, target);
    k_fft_yz_reduce<<<nsm, 1024, SMEM2C>>>((float*)d_out);
}

// round 17
// speedup vs baseline: 1.1374x; 1.0901x over previous
#include <cuda_runtime.h>
#include <cuda_fp16.h>
#include <math.h>

#define VOL (128*128*128)          // 2^21
#define NB 8                        // batch*channels
#define NUNITS (NB * 65)            // 520 pass-2 units
#define LUTN 8448                   // shell LUT entries (r2 <= 8320)

// Packed spectra FFT(o + i*t): [vol][p][z][y] where plane p holds true kx=rev7(p)
__device__ __half2 g_ft[(size_t)NB * VOL];
// Accumulators: c3*520 + shell*8 + bc
__device__ float g_acc[3 * 65 * NB];
__device__ unsigned g_done;
__device__ unsigned g_unit;        // dynamic work counter (reset by finalizer)

__device__ __forceinline__ int rev5(int i) { return (int)(__brev((unsigned)i) >> 27); }
__device__ __forceinline__ int rev7(int i) { return (int)(__brev((unsigned)i) >> 25); }

// ===========================================================================
// fp16 twiddle tables. Twiddle stored as pair (wr,wr),(-wi,wi).
// The 1/sqrt(128) ortho scale is folded into the m=2 stage table (twS[3]).
struct __align__(8) h2pair { __half2 rr, ii; };
#define TABS_H (64 + 32 + 128)

__device__ __forceinline__ void init_tabs_h(h2pair* twA, h2pair* twB, h2pair* twS, int tid) {
    const float K = -0.04908738521234052f;   // -2*pi/128
    const float SC = 0.08838834764831845f;   // 1/sqrt(128)
    if (tid < 64) {
        float sv, cv; sincosf(K * (float)tid, &sv, &cv);
        twA[tid].rr = __floats2half2_rn(cv, cv);
        twA[tid].ii = __floats2half2_rn(-sv, sv);
    }
    if (tid < 32) {
        float sv, cv; sincosf(K * (float)(2 * tid), &sv, &cv);
        twB[tid].rr = __floats2half2_rn(cv, cv);
        twB[tid].ii = __floats2half2_rn(-sv, sv);
#pragma unroll
        for (int j = 0; j < 4; j++) {
            int m = 16 >> j;
            float c2 = 1.0f, s2 = 0.0f;
            if (tid & m) {
                int idx = (tid & (m - 1)) * (64 / m);
                sincosf(K * (float)idx, &s2, &c2);
            }
            float g = (j == 3) ? SC : 1.0f;    // fold ortho scale into m=2 stage
            twS[j * 32 + tid].rr = __floats2half2_rn(c2 * g, c2 * g);
            twS[j * 32 + tid].ii = __floats2half2_rn(-s2 * g, s2 * g);
        }
    }
}

__device__ __forceinline__ __half2 cmul_h(h2pair w, __half2 v) {
    return __hfma2(w.ii, __lowhigh2highlow(v), __hmul2(w.rr, v));
}
__device__ __forceinline__ __half2 shflx_h2(__half2 v, int m) {
    unsigned u = *reinterpret_cast<unsigned*>(&v);
    u = __shfl_xor_sync(0xffffffffu, u, m);
    return *reinterpret_cast<__half2*>(&u);
}
__device__ __forceinline__ __half2 sgn_h2(int hi) {
    unsigned u = hi ? 0xBC00BC00u : 0x3C003C00u;   // (-1,-1) : (1,1)
    return *reinterpret_cast<__half2*>(&u);
}
__device__ __forceinline__ __half2 conj_h2(__half2 v) {
    unsigned c = 0xBC003C00u;                      // (1, -1)
    return __hmul2(v, *reinterpret_cast<__half2*>(&c));
}

// TWO interleaved 128-pt DIF FFTs in fp16x2 (shared twiddles, 2x ILP).
// Slot (lane,r) holds x[lane+32r] in, sc*X[rev7(lane+32r)] out.
__device__ __forceinline__ void dif_fft128_h2(__half2 v[4], __half2 u[4], int lane,
        const h2pair* twA, const h2pair* twB, const h2pair* twS) {
    __half2 a, b;
    {
        h2pair w0 = twA[lane], w1 = twA[lane + 32];
        a = v[0]; b = v[2]; v[0] = __hadd2(a, b); v[2] = cmul_h(w0, __hsub2(a, b));
        a = u[0]; b = u[2]; u[0] = __hadd2(a, b); u[2] = cmul_h(w0, __hsub2(a, b));
        a = v[1]; b = v[3]; v[1] = __hadd2(a, b); v[3] = cmul_h(w1, __hsub2(a, b));
        a = u[1]; b = u[3]; u[1] = __hadd2(a, b); u[3] = cmul_h(w1, __hsub2(a, b));
    }
    {
        h2pair w0 = twB[lane];
        a = v[0]; b = v[1]; v[0] = __hadd2(a, b); v[1] = cmul_h(w0, __hsub2(a, b));
        a = v[2]; b = v[3]; v[2] = __hadd2(a, b); v[3] = cmul_h(w0, __hsub2(a, b));
        a = u[0]; b = u[1]; u[0] = __hadd2(a, b); u[1] = cmul_h(w0, __hsub2(a, b));
        a = u[2]; b = u[3]; u[2] = __hadd2(a, b); u[3] = cmul_h(w0, __hsub2(a, b));
    }
#pragma unroll
    for (int j = 0; j < 4; j++) {
        int m = 16 >> j;
        __half2 sg = sgn_h2(lane & m);
        h2pair wj = twS[j * 32 + lane];
#pragma unroll
        for (int r = 0; r < 4; r++) {
            __half2 o1 = shflx_h2(v[r], m);
            __half2 o2 = shflx_h2(u[r], m);
            v[r] = cmul_h(wj, __hfma2(sg, v[r], o1));
            u[r] = cmul_h(wj, __hfma2(sg, u[r], o2));
        }
    }
    {
        __half2 sg = sgn_h2(lane & 1);
#pragma unroll
        for (int r = 0; r < 4; r++) {
            __half2 o1 = shflx_h2(v[r], 1);
            __half2 o2 = shflx_h2(u[r], 1);
            v[r] = __hfma2(sg, v[r], o1);
            u[r] = __hfma2(sg, u[r], o2);
        }
    }
}

// ---------------------------------------------------------------------------
// Pass 1: pack P = o + i*t (fp16), x-FFT fp16 (2 rows per warp, interleaved),
// transposed to [vol][p][z][y].
__global__ void __launch_bounds__(1024) k_fft_x(const float* __restrict__ a_in,
                                                const float* __restrict__ b_in) {
    __shared__ h2pair tabs[TABS_H];
    __shared__ __half2 tile[64][129];
    h2pair* twA = tabs; h2pair* twB = tabs + 64; h2pair* twS = tabs + 96;
    int tid = threadIdx.x, lane = tid & 31, w = tid >> 5;
    init_tabs_h(twA, twB, twS, tid);

    unsigned b = blockIdx.x;              // 8 vols * 128 z * 2 ytiles = 2048
    unsigned ytile = b & 1u;
    unsigned z     = (b >> 1) & 127u;
    unsigned vol   = b >> 8;

    size_t off = (size_t)vol * VOL + (size_t)z * 16384 + (size_t)(ytile * 64 + w) * 128;
    const float* so = a_in + off;
    const float* st = b_in + off;
    __syncthreads();

    __half2 v[4], u[4];
#pragma unroll
    for (int r = 0; r < 4; r++) {
        v[r] = __floats2half2_rn(so[lane + 32 * r],        st[lane + 32 * r]);
        u[r] = __floats2half2_rn(so[lane + 32 * r + 4096], st[lane + 32 * r + 4096]);
    }
    dif_fft128_h2(v, u, lane, twA, twB, twS);

#pragma unroll
    for (int r = 0; r < 4; r++) {
        tile[w][lane + 32 * r]      = v[r];
        tile[w + 32][lane + 32 * r] = u[r];
    }
    __syncthreads();

    size_t base = (size_t)vol * VOL + (size_t)z * 128 + ytile * 64 + lane;
#pragma unroll
    for (int xi = 0; xi < 4; xi++) {
        int p = w * 4 + xi;               // bit-reversed kx label
        g_ft[base + (size_t)p * 16384]      = tile[lane][p];
        g_ft[base + (size_t)p * 16384 + 32] = tile[lane + 32][p];
    }
}

// ---------------------------------------------------------------------------
// Pass 2 (PERSISTENT): each block loops over dynamically-fetched (bc,kx) units.
// Per unit: y-FFT reads directly from global into registers, writes to smem;
// z-FFT in registers (column + conj-mirror column, same-lane Hermitian
// pairing); fp32 shell reduce using a precomputed smem shell LUT (no sqrt).
#define SMEM2 (TABS_H * 8 + 2 * 128 * 129 * 4 + 32 * 196 * 4 + LUTN)

__global__ void __launch_bounds__(1024, 1) k_fft_yz_reduce(float* __restrict__ out) {
    extern __shared__ unsigned char smem_raw[];
    h2pair*  tabs = (h2pair*)smem_raw;
    h2pair*  twA = tabs; h2pair* twB = tabs + 64; h2pair* twS = tabs + 96;
    __half2* pA   = (__half2*)(tabs + TABS_H);            // [z][y] pitch 129
    __half2* pBs  = pA + 128 * 129;
    float*   bins = (float*)(pBs + 128 * 129);            // [warp][196]
    unsigned char* lut = (unsigned char*)(bins + 32 * 196); // shell LUT [LUTN]
    __shared__ unsigned s_unit;
    __shared__ bool s_last;
    __shared__ float red[NB];

    int tid = threadIdx.x, lane = tid & 31, w = tid >> 5;
    init_tabs_h(twA, twB, twS, tid);

    // shell LUT: lut[r2] = floor(sqrt(r2)) (exact for these magnitudes)
    for (int i = tid; i < LUTN; i += 1024)
        lut[i] = (unsigned char)(int)sqrtf((float)i);

    int qz = rev5(lane);
    int fz2[4];
    {
        int kzv[4] = { 4 * qz, 4 * qz + 2, 4 * qz + 1, 4 * qz + 3 };
#pragma unroll
        for (int r = 0; r < 4; r++) {
            int f = (kzv[r] >= 64) ? kzv[r] - 128 : kzv[r];
            fz2[r] = f * f;
        }
    }
    float* mybins = bins + w * 196;

    for (;;) {
        // fetch next unit + zero bins (bins reads of previous unit are behind
        // the post-fold barrier; LUT/tabs covered by first loop-top barrier)
        if (tid == 0) s_unit = atomicAdd(&g_unit, 1u);
        for (int i = tid; i < 32 * 196; i += 1024) bins[i] = 0.0f;
        __syncthreads();
        unsigned unit = s_unit;
        if (unit >= NUNITS) break;

        unsigned bc  = unit / 65;
        unsigned kx1 = unit % 65;                       // true kx 0..64
        unsigned kx2 = (128u - kx1) & 127u;
        bool dual = (kx2 != kx1);
        int p1 = rev7((int)kx1), p2 = rev7((int)kx2);
        __half2* pB = dual ? pBs : pA;

        const __half2* gA = g_ft + ((size_t)bc * 128 + p1) * 16384;
        const __half2* gB = g_ft + ((size_t)bc * 128 + p2) * 16384;

        // y-FFT: rows read straight from global, results to smem.
        if (dual) {
#pragma unroll
            for (int i = 0; i < 4; i++) {
                int z = w + 32 * i;
                __half2 v[4], u[4];
#pragma unroll
                for (int r = 0; r < 4; r++) {
                    v[r] = gA[z * 128 + lane + 32 * r];
                    u[r] = gB[z * 128 + lane + 32 * r];
                }
                dif_fft128_h2(v, u, lane, twA, twB, twS);
#pragma unroll
                for (int r = 0; r < 4; r++) {
                    pA [z * 129 + lane + 32 * r] = v[r];
                    pBs[z * 129 + lane + 32 * r] = u[r];
                }
            }
        } else {
#pragma unroll
            for (int i = 0; i < 2; i++) {
                int z0 = w + 64 * i, z1 = z0 + 32;
                __half2 v[4], u[4];
#pragma unroll
                for (int r = 0; r < 4; r++) {
                    v[r] = gA[z0 * 128 + lane + 32 * r];
                    u[r] = gA[z1 * 128 + lane + 32 * r];
                }
                dif_fft128_h2(v, u, lane, twA, twB, twS);
#pragma unroll
                for (int r = 0; r < 4; r++) {
                    pA[z0 * 129 + lane + 32 * r] = v[r];
                    pA[z1 * 129 + lane + 32 * r] = u[r];
                }
            }
        }
        __syncthreads();

        // z-FFT (fp16, registers). Mirror value F(-k) via FFT of the
        // CONJUGATED mirror column; conj folds into O/T sign flips.
        // slot (lane,r) holds kz = 4*rev5(lane) + {0,2,1,3}[r]
        int fx = (int)kx1; if (fx >= 64) fx -= 128;
        float cfac = dual ? 0.5f : 0.25f;     // z-norm inside the FFT scale

#pragma unroll
        for (int i = 0; i < 4; i++) {
            int pyA = w + 32 * i;                 // column position (bit-reversed ky)
            int kyA = rev7(pyA);
            int fy = (kyA >= 64) ? kyA - 128 : kyA;
            int fxy2 = fx * fx + fy * fy;
            if (fxy2 > 4224) continue;            // no shell <= 64 (warp-uniform)
            int pyB = rev7((128 - kyA) & 127);

            __half2 va[4], vh[4];
#pragma unroll
            for (int r = 0; r < 4; r++) {
                va[r] = pA[(lane + 32 * r) * 129 + pyA];
                vh[r] = conj_h2(pB[(lane + 32 * r) * 129 + pyB]);
            }
            dif_fft128_h2(va, vh, lane, twA, twB, twS);

#pragma unroll
            for (int r = 0; r < 4; r++) {
                int r2 = fz2[r] + fxy2;
                int sh = (int)lut[r2];             // floor(sqrt(r2)) via LUT
                if (sh <= 64) {
                    float2 F = __half22float2(va[r]);
                    float2 H = __half22float2(vh[r]);   // H = conj(F(-k))
                    float Ox = F.x + H.x, Oy = F.y + H.y;   // 2*O
                    float Tx = F.y - H.y, Ty = H.x - F.x;   // 2*T
                    atomicAdd(&mybins[sh * 3 + 0], Ox * Tx + Oy * Ty);
                    atomicAdd(&mybins[sh * 3 + 1], Ox * Ox + Oy * Oy);
                    atomicAdd(&mybins[sh * 3 + 2], Tx * Tx + Ty * Ty);
                }
            }
        }
        __syncthreads();

        // fold per-warp bins -> global accumulators (cfac applied once here)
        if (tid < 195) {
            float s = 0.0f;
#pragma unroll
            for (int ww = 0; ww < 32; ww++) s += bins[ww * 196 + tid];
            int sh = tid / 3, c3 = tid % 3;
            atomicAdd(&g_acc[c3 * 520 + sh * 8 + bc], s * cfac);
        }
        __syncthreads();    // fold reads complete before next unit's zeroing
    }

    // completion: last block computes loss and resets state (graph-replay safe)
    if (tid == 0) {
        __threadfence();
        unsigned old = atomicAdd(&g_done, 1u);
        s_last = (old == gridDim.x - 1);
    }
    __syncthreads();
    if (!s_last) return;

    float* sacc = bins;
    for (int i = tid; i < 3 * 65 * NB; i += 1024)
        sacc[i] = atomicExch(&g_acc[i], 0.0f);
    __syncthreads();

    if (tid < NB) {
        float acc = 0.0f;
        for (int s = 1; s <= 64; s++) {
            float n  = sacc[0 * 520 + s * 8 + tid];
            float po = sacc[1 * 520 + s * 8 + tid];
            float pt = sacc[2 * 520 + s * 8 + tid];
            float f = n / sqrtf(po * pt + 1e-6f);
            acc += fminf(1.0f, fmaxf(-1.0f, f));
        }
        red[tid] = 1.0f - acc * (1.0f / 64.0f);
    }
    __syncthreads();
    if (tid == 0) {
        float m = 0.0f;
#pragma unroll
        for (int i = 0; i < NB; i++) m += red[i];
        out[0] = m * (1.0f / (float)NB);
        atomicExch(&g_unit, 0u);
        atomicExch(&g_done, 0u);
    }
}

// ---------------------------------------------------------------------------
extern "C" void kernel_launch(void* const* d_in, const int* in_sizes, int n_in,
                              void* d_out, int out_size) {
    const float* model_output = (const float*)d_in[0];
    const float* target       = (const float*)d_in[1];

    static int nsm = 0;
    if (nsm == 0) {
        int dev = 0;
        cudaGetDevice(&dev);
        if (cudaDeviceGetAttribute(&nsm, cudaDevAttrMultiProcessorCount, dev)
                != cudaSuccess || nsm <= 0)
            nsm = 148;
    }

    cudaFuncSetAttribute(k_fft_yz_reduce,
                         cudaFuncAttributeMaxDynamicSharedMemorySize, SMEM2);

    k_fft_x<<<8 * 128 * 2, 1024>>>(model_output, target);
    k_fft_yz_reduce<<<nsm, 1024, SMEM2>>>((float*)d_out);
}